// round 3
// baseline (speedup 1.0000x reference)
#include <cuda_runtime.h>
#include <cuda_bf16.h>
#include <math.h>
#include <stdint.h>

#define NN 100000
#define EE 1600000
#define D  128
#define HEADS 4
#define CH 32
#define NEG_SLOPE 0.2f
#define CAP 128   // per-node bucket capacity; deg ~ Poisson(16), P(>128) ~ 1e-60

// ---------------- scratch ------------------------------------------------------
__device__ float g_bufA[NN * D];
__device__ float g_bufB[NN * D];
__device__ float g_xr[NN * D];
__device__ float g_ss[NN * HEADS];
__device__ float g_sd[NN * HEADS];
__device__ int   g_cnt[NN];              // statically zero; re-zeroed by agg2 each launch
__device__ int   g_sorted_src[NN * CAP]; // bucketed by destination

// ---------------- scatter (count + bucket in one pass, inline dtype detect) ----
__global__ void __launch_bounds__(256) scatter_kernel(const void* __restrict__ ei) {
    __shared__ int s64;
    if (threadIdx.x == 0) s64 = 1;
    __syncthreads();
    if (threadIdx.x < 256) {
        // int64 input => odd 32-bit words (high halves) are all 0.
        // int32 input => odd words are random node ids (nonzero w.h.p.).
        if (((const unsigned int*)ei)[2 * threadIdx.x + 1] != 0u) s64 = 0;
    }
    __syncthreads();

    int i = blockIdx.x * blockDim.x + threadIdx.x;
    if (i >= EE) return;
    int s, d;
    if (s64) {
        s = (int)((const long long*)ei)[i];
        d = (int)((const long long*)ei)[(long long)EE + i];
    } else {
        s = ((const int*)ei)[i];
        d = ((const int*)ei)[EE + i];
    }
    int pos = atomicAdd(&g_cnt[d], 1);
    if (pos < CAP) g_sorted_src[d * CAP + pos] = s;
}

// ---------------- tf32 tensor-core GEMM ----------------------------------------
__device__ __forceinline__ float to_tf32(float x) {
    uint32_t u;
    asm("cvt.rna.tf32.f32 %0, %1;" : "=r"(u) : "f"(x));
    return __uint_as_float(u);
}

#define MMA_TF32(c, av, bv)                                                  \
    asm volatile(                                                            \
        "mma.sync.aligned.m16n8k8.row.col.f32.tf32.tf32.f32 "                \
        "{%0,%1,%2,%3},{%4,%5,%6,%7},{%8,%9},{%0,%1,%2,%3};"                 \
        : "+f"((c)[0]), "+f"((c)[1]), "+f"((c)[2]), "+f"((c)[3])             \
        : "r"((av)[0]), "r"((av)[1]), "r"((av)[2]), "r"((av)[3]),            \
          "r"((bv)[0]), "r"((bv)[1]))

// block: 256 thr = 8 warps as 2(M) x 4(N); block tile 128x128; warp tile 64x32
template<bool SCORES>
__global__ void __launch_bounds__(256) gemm_tc_kernel(
    const float* __restrict__ A, const float* __restrict__ W,
    const float* __restrict__ a_src, const float* __restrict__ a_dst,
    float* __restrict__ out, float* __restrict__ ssrc, float* __restrict__ sdst)
{
    __shared__ float AsT[32][132];
    __shared__ float Ws[32][132];

    const int tid  = threadIdx.x;
    const int warp = tid >> 5, lane = tid & 31;
    const int g = lane >> 2, t = lane & 3;
    const int wm = warp >> 2;
    const int wn = warp & 3;          // == head for SCORES
    const int m0 = wm * 64, n0 = wn * 32;
    const int row0 = blockIdx.x * 128;

    float acc[4][4][4];
#pragma unroll
    for (int i = 0; i < 4; ++i)
#pragma unroll
        for (int j = 0; j < 4; ++j)
#pragma unroll
            for (int k = 0; k < 4; ++k) acc[i][j][k] = 0.f;

    for (int kc = 0; kc < D; kc += 32) {
#pragma unroll
        for (int it = 0; it < 4; ++it) {
            int idx = tid + it * 256;
            int r = idx >> 3;
            int q = idx & 7;
            int row = row0 + r;
            float4 v = make_float4(0.f, 0.f, 0.f, 0.f);
            if (row < NN) v = *(const float4*)&A[(long long)row * D + kc + q * 4];
            AsT[q * 4 + 0][r] = to_tf32(v.x);
            AsT[q * 4 + 1][r] = to_tf32(v.y);
            AsT[q * 4 + 2][r] = to_tf32(v.z);
            AsT[q * 4 + 3][r] = to_tf32(v.w);
        }
#pragma unroll
        for (int it = 0; it < 4; ++it) {
            int idx = tid + it * 256;
            int kr = idx >> 5;
            int c4 = idx & 31;
            float4 v = *(const float4*)&W[(kc + kr) * D + c4 * 4];
            Ws[kr][c4 * 4 + 0] = to_tf32(v.x);
            Ws[kr][c4 * 4 + 1] = to_tf32(v.y);
            Ws[kr][c4 * 4 + 2] = to_tf32(v.z);
            Ws[kr][c4 * 4 + 3] = to_tf32(v.w);
        }
        __syncthreads();
#pragma unroll
        for (int ks = 0; ks < 32; ks += 8) {
            uint32_t a[4][4], b[4][2];
#pragma unroll
            for (int mt = 0; mt < 4; ++mt) {
                int mr = m0 + mt * 16 + g;
                a[mt][0] = __float_as_uint(AsT[ks + t][mr]);
                a[mt][1] = __float_as_uint(AsT[ks + t][mr + 8]);
                a[mt][2] = __float_as_uint(AsT[ks + t + 4][mr]);
                a[mt][3] = __float_as_uint(AsT[ks + t + 4][mr + 8]);
            }
#pragma unroll
            for (int nt = 0; nt < 4; ++nt) {
                int nc = n0 + nt * 8 + g;
                b[nt][0] = __float_as_uint(Ws[ks + t][nc]);
                b[nt][1] = __float_as_uint(Ws[ks + t + 4][nc]);
            }
#pragma unroll
            for (int mt = 0; mt < 4; ++mt)
#pragma unroll
                for (int nt = 0; nt < 4; ++nt)
                    MMA_TF32(acc[mt][nt], a[mt], b[nt]);
        }
        __syncthreads();
    }

    float2 asv[4], adv[4];
    if (SCORES) {
#pragma unroll
        for (int nt = 0; nt < 4; ++nt) {
            int c = nt * 8 + 2 * t;
            asv[nt] = make_float2(a_src[wn * CH + c], a_src[wn * CH + c + 1]);
            adv[nt] = make_float2(a_dst[wn * CH + c], a_dst[wn * CH + c + 1]);
        }
    }
#pragma unroll
    for (int mt = 0; mt < 4; ++mt) {
        int r_lo = row0 + m0 + mt * 16 + g;
        int r_hi = r_lo + 8;
        float su_lo = 0.f, du_lo = 0.f, su_hi = 0.f, du_hi = 0.f;
#pragma unroll
        for (int nt = 0; nt < 4; ++nt) {
            int col = n0 + nt * 8 + 2 * t;
            if (r_lo < NN)
                *(float2*)&out[(long long)r_lo * D + col] =
                    make_float2(acc[mt][nt][0], acc[mt][nt][1]);
            if (r_hi < NN)
                *(float2*)&out[(long long)r_hi * D + col] =
                    make_float2(acc[mt][nt][2], acc[mt][nt][3]);
            if (SCORES) {
                su_lo += acc[mt][nt][0] * asv[nt].x + acc[mt][nt][1] * asv[nt].y;
                du_lo += acc[mt][nt][0] * adv[nt].x + acc[mt][nt][1] * adv[nt].y;
                su_hi += acc[mt][nt][2] * asv[nt].x + acc[mt][nt][3] * asv[nt].y;
                du_hi += acc[mt][nt][2] * adv[nt].x + acc[mt][nt][3] * adv[nt].y;
            }
        }
        if (SCORES) {
#pragma unroll
            for (int off = 1; off <= 2; off <<= 1) {
                su_lo += __shfl_xor_sync(0xffffffffu, su_lo, off);
                du_lo += __shfl_xor_sync(0xffffffffu, du_lo, off);
                su_hi += __shfl_xor_sync(0xffffffffu, su_hi, off);
                du_hi += __shfl_xor_sync(0xffffffffu, du_hi, off);
            }
            if (t == 0) {
                if (r_lo < NN) { ssrc[r_lo * HEADS + wn] = su_lo; sdst[r_lo * HEADS + wn] = du_lo; }
                if (r_hi < NN) { ssrc[r_hi * HEADS + wn] = su_hi; sdst[r_hi * HEADS + wn] = du_hi; }
            }
        }
    }
}

// ---------------- softmax + aggregation (self-loop handled inline) --------------
__device__ __forceinline__ float lrelu(float v) { return v > 0.f ? v : NEG_SLOPE * v; }

template<int LAYER>
__global__ void __launch_bounds__(256) agg_kernel(
    const float* __restrict__ h,
    const float* __restrict__ ss,
    const float* __restrict__ sd,
    const float* __restrict__ bias,
    float* __restrict__ out,
    const float* __restrict__ xr,
    const float* __restrict__ br)
{
    __shared__ float4 elc[8][CAP];   // leaky-relu logits, then exp(el-m)
    __shared__ int    srcc[8][CAP];

    int warp = (blockIdx.x * blockDim.x + threadIdx.x) >> 5;
    int wip  = threadIdx.x >> 5;
    int lane = threadIdx.x & 31;
    if (warp >= NN) return;
    int n = warp;

    int deg;
    if (lane == 0) {
        deg = g_cnt[n];
        if (LAYER == 2) g_cnt[n] = 0;   // reset for next graph replay
    }
    deg = __shfl_sync(0xffffffffu, deg, 0);
    deg = min(deg, CAP);
    const int* __restrict__ srcp = &g_sorted_src[n * CAP];

    float4 sdv = *(const float4*)&sd[n * HEADS];
    float4 ssn = *(const float4*)&ss[n * HEADS];
    float4 els = make_float4(lrelu(ssn.x + sdv.x), lrelu(ssn.y + sdv.y),
                             lrelu(ssn.z + sdv.z), lrelu(ssn.w + sdv.w));

    // pass 1: gather scores, cache logits, track max (self-loop seeds max)
    float m0 = els.x, m1 = els.y, m2 = els.z, m3 = els.w;
    for (int i = lane; i < deg; i += 32) {
        int s = srcp[i];
        float4 sv = *(const float4*)&ss[s * HEADS];
        float4 el = make_float4(lrelu(sv.x + sdv.x), lrelu(sv.y + sdv.y),
                                lrelu(sv.z + sdv.z), lrelu(sv.w + sdv.w));
        elc[wip][i] = el;
        srcc[wip][i] = s;
        m0 = fmaxf(m0, el.x); m1 = fmaxf(m1, el.y);
        m2 = fmaxf(m2, el.z); m3 = fmaxf(m3, el.w);
    }
#pragma unroll
    for (int off = 16; off; off >>= 1) {
        m0 = fmaxf(m0, __shfl_xor_sync(0xffffffffu, m0, off));
        m1 = fmaxf(m1, __shfl_xor_sync(0xffffffffu, m1, off));
        m2 = fmaxf(m2, __shfl_xor_sync(0xffffffffu, m2, off));
        m3 = fmaxf(m3, __shfl_xor_sync(0xffffffffu, m3, off));
    }
    __syncwarp();

    // pass 2: exp(el-m) into smem; denom
    float d0 = 0.f, d1 = 0.f, d2 = 0.f, d3 = 0.f;
    for (int i = lane; i < deg; i += 32) {
        float4 el = elc[wip][i];
        float4 e4 = make_float4(__expf(el.x - m0), __expf(el.y - m1),
                                __expf(el.z - m2), __expf(el.w - m3));
        elc[wip][i] = e4;
        d0 += e4.x; d1 += e4.y; d2 += e4.z; d3 += e4.w;
    }
#pragma unroll
    for (int off = 16; off; off >>= 1) {
        d0 += __shfl_xor_sync(0xffffffffu, d0, off);
        d1 += __shfl_xor_sync(0xffffffffu, d1, off);
        d2 += __shfl_xor_sync(0xffffffffu, d2, off);
        d3 += __shfl_xor_sync(0xffffffffu, d3, off);
    }
    // self-loop exp (uniform across lanes post-reduce)
    float es0 = __expf(els.x - m0), es1 = __expf(els.y - m1);
    float es2 = __expf(els.z - m2), es3 = __expf(els.w - m3);
    d0 += es0; d1 += es1; d2 += es2; d3 += es3;
    __syncwarp();

    // pass 3: weighted gather; lane owns 4 channels of head hd
    int hd = lane >> 3;
    int c0 = lane * 4;
    float dh  = (hd == 0) ? d0 : (hd == 1) ? d1 : (hd == 2) ? d2 : d3;
    float esh = (hd == 0) ? es0 : (hd == 1) ? es1 : (hd == 2) ? es2 : es3;
    float inv_dh = 1.f / dh;

    // self-loop contribution
    float a_self = esh * inv_dh;
    float4 hn = *(const float4*)&h[(long long)n * D + c0];
    float ax = a_self * hn.x, ay = a_self * hn.y;
    float az = a_self * hn.z, aw = a_self * hn.w;

#pragma unroll 4
    for (int i = 0; i < deg; ++i) {
        int s = srcc[wip][i];
        float4 e4 = elc[wip][i];
        float eh = (hd == 0) ? e4.x : (hd == 1) ? e4.y : (hd == 2) ? e4.z : e4.w;
        float alpha = eh * inv_dh;
        float4 hv = *(const float4*)&h[(long long)s * D + c0];
        ax += alpha * hv.x; ay += alpha * hv.y;
        az += alpha * hv.z; aw += alpha * hv.w;
    }

    float4 b = *(const float4*)&bias[c0];
    if (LAYER == 1) {
        float4 o = make_float4(fmaxf(ax + b.x, 0.f), fmaxf(ay + b.y, 0.f),
                               fmaxf(az + b.z, 0.f), fmaxf(aw + b.w, 0.f));
        *(float4*)&out[(long long)n * D + c0] = o;
    } else {
        float4 r  = *(const float4*)&xr[(long long)n * D + c0];
        float4 bb = *(const float4*)&br[c0];
        float4 o = make_float4(ax + b.x + r.x + bb.x, ay + b.y + r.y + bb.y,
                               az + b.z + r.z + bb.z, aw + b.w + r.w + bb.w);
        *(float4*)&out[(long long)n * D + c0] = o;
    }
}

// ---------------- launch --------------------------------------------------------
extern "C" void kernel_launch(void* const* d_in, const int* in_sizes, int n_in,
                              void* d_out, int out_size) {
    const float* x   = (const float*)d_in[0];
    const void*  ei  = d_in[1];
    const float* W1  = (const float*)d_in[2];
    const float* a1s = (const float*)d_in[3];
    const float* a1d = (const float*)d_in[4];
    const float* b1  = (const float*)d_in[5];
    const float* W2  = (const float*)d_in[6];
    const float* a2s = (const float*)d_in[7];
    const float* a2d = (const float*)d_in[8];
    const float* b2  = (const float*)d_in[9];
    const float* Wr  = (const float*)d_in[10];
    const float* br  = (const float*)d_in[11];
    float* out = (float*)d_out;

    float* bufA; cudaGetSymbolAddress((void**)&bufA, g_bufA);
    float* bufB; cudaGetSymbolAddress((void**)&bufB, g_bufB);
    float* xr;   cudaGetSymbolAddress((void**)&xr, g_xr);
    float* ssp;  cudaGetSymbolAddress((void**)&ssp, g_ss);
    float* sdp;  cudaGetSymbolAddress((void**)&sdp, g_sd);

    const int gemm_grid = (NN + 127) / 128;

    // 1: bucketed counting scatter (g_cnt starts zero; agg2 re-zeroes it)
    scatter_kernel<<<(EE + 255) / 256, 256>>>(ei);
    // 2: layer-1 transform + fused scores
    gemm_tc_kernel<true><<<gemm_grid, 256>>>(x, W1, a1s, a1d, bufA, ssp, sdp);
    // 3: residual transform
    gemm_tc_kernel<false><<<gemm_grid, 256>>>(x, Wr, nullptr, nullptr, xr, nullptr, nullptr);
    // 4: layer-1 aggregation (profiling slot)
    agg_kernel<1><<<(NN + 7) / 8, 256>>>(bufA, ssp, sdp, b1, bufB, nullptr, nullptr);
    // 5: layer-2 transform + fused scores
    gemm_tc_kernel<true><<<gemm_grid, 256>>>(bufB, W2, a2s, a2d, bufA, ssp, sdp);
    // 6: layer-2 aggregation + residual (+ cnt reset)
    agg_kernel<2><<<(NN + 7) / 8, 256>>>(bufA, ssp, sdp, b2, out, xr, br);
}

// round 4
// speedup vs baseline: 1.9355x; 1.9355x over previous
#include <cuda_runtime.h>
#include <cuda_bf16.h>
#include <math.h>
#include <stdint.h>

#define NN 100000
#define EE 1600000
#define D  128
#define HEADS 4
#define CH 32
#define NEG_SLOPE 0.2f
#define CAP 128                        // smem cache cap; deg ~ Poisson(16)
#define NB_SCAN ((NN + 1023) / 1024)   // 98

// ---------------- scratch ------------------------------------------------------
__device__ float g_bufA[NN * D];
__device__ float g_bufB[NN * D];
__device__ float g_xr[NN * D];
__device__ float g_ss[NN * HEADS];
__device__ float g_sd[NN * HEADS];
__device__ int   g_deg[NN];            // statically zero; agg2 re-zeroes each launch
__device__ int   g_offs[NN + 1];
__device__ int   g_cursor[NN];
__device__ int   g_sorted_src[EE];     // compact, sorted by destination
__device__ int   g_bsum[NB_SCAN];
__device__ int   g_bpre[NB_SCAN];

// ---------------- edge dtype detection (per-block, inline) ----------------------
// int64 input => odd 32-bit words (high halves) all zero; int32 => random ids.
__device__ __forceinline__ int detect_s64(const void* ei, int* smem_flag) {
    if (threadIdx.x == 0) *smem_flag = 1;
    __syncthreads();
    if (threadIdx.x < 256)
        if (((const unsigned int*)ei)[2 * threadIdx.x + 1] != 0u) *smem_flag = 0;
    __syncthreads();
    return *smem_flag;
}

// ---------------- counting sort (destinations only; self-loops inline later) ----
__global__ void __launch_bounds__(256) count_kernel(const void* __restrict__ ei) {
    __shared__ int s64s;
    int s64 = detect_s64(ei, &s64s);
    int i = blockIdx.x * blockDim.x + threadIdx.x;
    if (i >= EE) return;
    int d = s64 ? (int)((const long long*)ei)[(long long)EE + i]
                : ((const int*)ei)[EE + i];
    atomicAdd(&g_deg[d], 1);
}

__global__ void __launch_bounds__(256) scan_k1() {
    __shared__ int sm[256];
    int b = blockIdx.x, tid = threadIdx.x;
    int base = b * 1024 + tid * 4;
    int s = 0;
#pragma unroll
    for (int j = 0; j < 4; ++j) {
        int idx = base + j;
        if (idx < NN) s += g_deg[idx];
    }
    sm[tid] = s;
    __syncthreads();
    for (int off = 128; off; off >>= 1) {
        if (tid < off) sm[tid] += sm[tid + off];
        __syncthreads();
    }
    if (tid == 0) g_bsum[b] = sm[0];
}

__global__ void scan_k2() {
    __shared__ int sm[128];
    int tid = threadIdx.x;
    sm[tid] = (tid < NB_SCAN) ? g_bsum[tid] : 0;
    __syncthreads();
    for (int off = 1; off < 128; off <<= 1) {
        int v = (tid >= off) ? sm[tid - off] : 0;
        __syncthreads();
        sm[tid] += v;
        __syncthreads();
    }
    if (tid < NB_SCAN) g_bpre[tid] = (tid == 0) ? 0 : sm[tid - 1];
    if (tid == 0) g_offs[NN] = EE;
}

__global__ void __launch_bounds__(256) scan_k3() {
    __shared__ int sm[256];
    int b = blockIdx.x, tid = threadIdx.x;
    int base = b * 1024 + tid * 4;
    int v[4];
#pragma unroll
    for (int j = 0; j < 4; ++j) {
        int idx = base + j;
        v[j] = (idx < NN) ? g_deg[idx] : 0;
    }
    int tot = v[0] + v[1] + v[2] + v[3];
    sm[tid] = tot;
    __syncthreads();
    for (int off = 1; off < 256; off <<= 1) {
        int x = (tid >= off) ? sm[tid - off] : 0;
        __syncthreads();
        sm[tid] += x;
        __syncthreads();
    }
    int run = g_bpre[b] + ((tid == 0) ? 0 : sm[tid - 1]);
#pragma unroll
    for (int j = 0; j < 4; ++j) {
        int idx = base + j;
        if (idx < NN) {
            g_offs[idx]   = run;
            g_cursor[idx] = run;
            run += v[j];
        }
    }
}

__global__ void __launch_bounds__(256) scatter_kernel(const void* __restrict__ ei) {
    __shared__ int s64s;
    int s64 = detect_s64(ei, &s64s);
    int i = blockIdx.x * blockDim.x + threadIdx.x;
    if (i >= EE) return;
    int s, d;
    if (s64) {
        s = (int)((const long long*)ei)[i];
        d = (int)((const long long*)ei)[(long long)EE + i];
    } else {
        s = ((const int*)ei)[i];
        d = ((const int*)ei)[EE + i];
    }
    int pos = atomicAdd(&g_cursor[d], 1);
    g_sorted_src[pos] = s;
}

// ---------------- tf32 tensor-core GEMMs ----------------------------------------
__device__ __forceinline__ float to_tf32(float x) {
    uint32_t u;
    asm("cvt.rna.tf32.f32 %0, %1;" : "=r"(u) : "f"(x));
    return __uint_as_float(u);
}

#define MMA_TF32(c, av, bv)                                                  \
    asm volatile(                                                            \
        "mma.sync.aligned.m16n8k8.row.col.f32.tf32.tf32.f32 "                \
        "{%0,%1,%2,%3},{%4,%5,%6,%7},{%8,%9},{%0,%1,%2,%3};"                 \
        : "+f"((c)[0]), "+f"((c)[1]), "+f"((c)[2]), "+f"((c)[3])             \
        : "r"((av)[0]), "r"((av)[1]), "r"((av)[2]), "r"((av)[3]),            \
          "r"((bv)[0]), "r"((bv)[1]))

// ---- single-output GEMM with fused scores (layer 2) ----------------------------
// block: 256 thr = 8 warps as 2(M) x 4(N); block tile 128x128; warp tile 64x32
template<bool SCORES>
__global__ void __launch_bounds__(256) gemm_tc_kernel(
    const float* __restrict__ A, const float* __restrict__ W,
    const float* __restrict__ a_src, const float* __restrict__ a_dst,
    float* __restrict__ out, float* __restrict__ ssrc, float* __restrict__ sdst)
{
    __shared__ float AsT[32][132];
    __shared__ float Ws[32][132];

    const int tid  = threadIdx.x;
    const int warp = tid >> 5, lane = tid & 31;
    const int g = lane >> 2, t = lane & 3;
    const int wm = warp >> 2;
    const int wn = warp & 3;
    const int m0 = wm * 64, n0 = wn * 32;
    const int row0 = blockIdx.x * 128;

    float acc[4][4][4];
#pragma unroll
    for (int i = 0; i < 4; ++i)
#pragma unroll
        for (int j = 0; j < 4; ++j)
#pragma unroll
            for (int k = 0; k < 4; ++k) acc[i][j][k] = 0.f;

    for (int kc = 0; kc < D; kc += 32) {
#pragma unroll
        for (int it = 0; it < 4; ++it) {
            int idx = tid + it * 256;
            int r = idx >> 3, q = idx & 7;
            int row = row0 + r;
            float4 v = make_float4(0.f, 0.f, 0.f, 0.f);
            if (row < NN) v = *(const float4*)&A[(long long)row * D + kc + q * 4];
            AsT[q * 4 + 0][r] = to_tf32(v.x);
            AsT[q * 4 + 1][r] = to_tf32(v.y);
            AsT[q * 4 + 2][r] = to_tf32(v.z);
            AsT[q * 4 + 3][r] = to_tf32(v.w);
        }
#pragma unroll
        for (int it = 0; it < 4; ++it) {
            int idx = tid + it * 256;
            int kr = idx >> 5, c4 = idx & 31;
            float4 v = *(const float4*)&W[(kc + kr) * D + c4 * 4];
            Ws[kr][c4 * 4 + 0] = to_tf32(v.x);
            Ws[kr][c4 * 4 + 1] = to_tf32(v.y);
            Ws[kr][c4 * 4 + 2] = to_tf32(v.z);
            Ws[kr][c4 * 4 + 3] = to_tf32(v.w);
        }
        __syncthreads();
#pragma unroll
        for (int ks = 0; ks < 32; ks += 8) {
            uint32_t a[4][4], b[4][2];
#pragma unroll
            for (int mt = 0; mt < 4; ++mt) {
                int mr = m0 + mt * 16 + g;
                a[mt][0] = __float_as_uint(AsT[ks + t][mr]);
                a[mt][1] = __float_as_uint(AsT[ks + t][mr + 8]);
                a[mt][2] = __float_as_uint(AsT[ks + t + 4][mr]);
                a[mt][3] = __float_as_uint(AsT[ks + t + 4][mr + 8]);
            }
#pragma unroll
            for (int nt = 0; nt < 4; ++nt) {
                int nc = n0 + nt * 8 + g;
                b[nt][0] = __float_as_uint(Ws[ks + t][nc]);
                b[nt][1] = __float_as_uint(Ws[ks + t + 4][nc]);
            }
#pragma unroll
            for (int mt = 0; mt < 4; ++mt)
#pragma unroll
                for (int nt = 0; nt < 4; ++nt)
                    MMA_TF32(acc[mt][nt], a[mt], b[nt]);
        }
        __syncthreads();
    }

    float2 asv[4], adv[4];
    if (SCORES) {
#pragma unroll
        for (int nt = 0; nt < 4; ++nt) {
            int c = nt * 8 + 2 * t;
            asv[nt] = make_float2(a_src[wn * CH + c], a_src[wn * CH + c + 1]);
            adv[nt] = make_float2(a_dst[wn * CH + c], a_dst[wn * CH + c + 1]);
        }
    }
#pragma unroll
    for (int mt = 0; mt < 4; ++mt) {
        int r_lo = row0 + m0 + mt * 16 + g;
        int r_hi = r_lo + 8;
        float su_lo = 0.f, du_lo = 0.f, su_hi = 0.f, du_hi = 0.f;
#pragma unroll
        for (int nt = 0; nt < 4; ++nt) {
            int col = n0 + nt * 8 + 2 * t;
            if (r_lo < NN)
                *(float2*)&out[(long long)r_lo * D + col] =
                    make_float2(acc[mt][nt][0], acc[mt][nt][1]);
            if (r_hi < NN)
                *(float2*)&out[(long long)r_hi * D + col] =
                    make_float2(acc[mt][nt][2], acc[mt][nt][3]);
            if (SCORES) {
                su_lo += acc[mt][nt][0] * asv[nt].x + acc[mt][nt][1] * asv[nt].y;
                du_lo += acc[mt][nt][0] * adv[nt].x + acc[mt][nt][1] * adv[nt].y;
                su_hi += acc[mt][nt][2] * asv[nt].x + acc[mt][nt][3] * asv[nt].y;
                du_hi += acc[mt][nt][2] * adv[nt].x + acc[mt][nt][3] * adv[nt].y;
            }
        }
        if (SCORES) {
#pragma unroll
            for (int off = 1; off <= 2; off <<= 1) {
                su_lo += __shfl_xor_sync(0xffffffffu, su_lo, off);
                du_lo += __shfl_xor_sync(0xffffffffu, du_lo, off);
                su_hi += __shfl_xor_sync(0xffffffffu, su_hi, off);
                du_hi += __shfl_xor_sync(0xffffffffu, du_hi, off);
            }
            if (t == 0) {
                if (r_lo < NN) { ssrc[r_lo * HEADS + wn] = su_lo; sdst[r_lo * HEADS + wn] = du_lo; }
                if (r_hi < NN) { ssrc[r_hi * HEADS + wn] = su_hi; sdst[r_hi * HEADS + wn] = du_hi; }
            }
        }
    }
}

// ---- dual-output GEMM: [x@W1 | x@Wr] in one pass over x (layer 1 + residual) ----
// block: 512 thr = 16 warps as 2(M) x 8(N); block tile 128x256; warp tile 64x32
__global__ void __launch_bounds__(512) gemm_dual_kernel(
    const float* __restrict__ A,
    const float* __restrict__ W1, const float* __restrict__ Wr,
    const float* __restrict__ a_src, const float* __restrict__ a_dst,
    float* __restrict__ out1, float* __restrict__ outr,
    float* __restrict__ ssrc, float* __restrict__ sdst)
{
    __shared__ float AsT[32][132];
    __shared__ float Ws[32][260];

    const int tid  = threadIdx.x;
    const int warp = tid >> 5, lane = tid & 31;
    const int g = lane >> 2, t = lane & 3;
    const int wm = warp >> 3;          // 0..1
    const int wn = warp & 7;           // 0..7 ; wn<4 -> W1 cols (head=wn), else Wr
    const int m0 = wm * 64, n0 = wn * 32;
    const int row0 = blockIdx.x * 128;

    float acc[4][4][4];
#pragma unroll
    for (int i = 0; i < 4; ++i)
#pragma unroll
        for (int j = 0; j < 4; ++j)
#pragma unroll
            for (int k = 0; k < 4; ++k) acc[i][j][k] = 0.f;

    for (int kc = 0; kc < D; kc += 32) {
#pragma unroll
        for (int it = 0; it < 2; ++it) {
            int idx = tid + it * 512;    // 0..1023
            int r = idx >> 3, q = idx & 7;
            int row = row0 + r;
            float4 v = make_float4(0.f, 0.f, 0.f, 0.f);
            if (row < NN) v = *(const float4*)&A[(long long)row * D + kc + q * 4];
            AsT[q * 4 + 0][r] = to_tf32(v.x);
            AsT[q * 4 + 1][r] = to_tf32(v.y);
            AsT[q * 4 + 2][r] = to_tf32(v.z);
            AsT[q * 4 + 3][r] = to_tf32(v.w);
        }
#pragma unroll
        for (int it = 0; it < 4; ++it) {
            int idx = tid + it * 512;    // 0..2047
            int kr = idx >> 6;           // 0..31
            int c4 = idx & 63;           // 0..63 (64 float4 = 256 cols)
            float4 v;
            if (c4 < 32) v = *(const float4*)&W1[(kc + kr) * D + c4 * 4];
            else         v = *(const float4*)&Wr[(kc + kr) * D + (c4 - 32) * 4];
            Ws[kr][c4 * 4 + 0] = to_tf32(v.x);
            Ws[kr][c4 * 4 + 1] = to_tf32(v.y);
            Ws[kr][c4 * 4 + 2] = to_tf32(v.z);
            Ws[kr][c4 * 4 + 3] = to_tf32(v.w);
        }
        __syncthreads();
#pragma unroll
        for (int ks = 0; ks < 32; ks += 8) {
            uint32_t a[4][4], b[4][2];
#pragma unroll
            for (int mt = 0; mt < 4; ++mt) {
                int mr = m0 + mt * 16 + g;
                a[mt][0] = __float_as_uint(AsT[ks + t][mr]);
                a[mt][1] = __float_as_uint(AsT[ks + t][mr + 8]);
                a[mt][2] = __float_as_uint(AsT[ks + t + 4][mr]);
                a[mt][3] = __float_as_uint(AsT[ks + t + 4][mr + 8]);
            }
#pragma unroll
            for (int nt = 0; nt < 4; ++nt) {
                int nc = n0 + nt * 8 + g;
                b[nt][0] = __float_as_uint(Ws[ks + t][nc]);
                b[nt][1] = __float_as_uint(Ws[ks + t + 4][nc]);
            }
#pragma unroll
            for (int mt = 0; mt < 4; ++mt)
#pragma unroll
                for (int nt = 0; nt < 4; ++nt)
                    MMA_TF32(acc[mt][nt], a[mt], b[nt]);
        }
        __syncthreads();
    }

    const bool is1 = (wn < 4);
    float* outp = is1 ? out1 : outr;
    const int cbase = is1 ? n0 : (n0 - 128);
    float2 asv[4], adv[4];
    if (is1) {
#pragma unroll
        for (int nt = 0; nt < 4; ++nt) {
            int c = nt * 8 + 2 * t;
            asv[nt] = make_float2(a_src[wn * CH + c], a_src[wn * CH + c + 1]);
            adv[nt] = make_float2(a_dst[wn * CH + c], a_dst[wn * CH + c + 1]);
        }
    }
#pragma unroll
    for (int mt = 0; mt < 4; ++mt) {
        int r_lo = row0 + m0 + mt * 16 + g;
        int r_hi = r_lo + 8;
        float su_lo = 0.f, du_lo = 0.f, su_hi = 0.f, du_hi = 0.f;
#pragma unroll
        for (int nt = 0; nt < 4; ++nt) {
            int col = cbase + nt * 8 + 2 * t;
            if (r_lo < NN)
                *(float2*)&outp[(long long)r_lo * D + col] =
                    make_float2(acc[mt][nt][0], acc[mt][nt][1]);
            if (r_hi < NN)
                *(float2*)&outp[(long long)r_hi * D + col] =
                    make_float2(acc[mt][nt][2], acc[mt][nt][3]);
            if (is1) {
                su_lo += acc[mt][nt][0] * asv[nt].x + acc[mt][nt][1] * asv[nt].y;
                du_lo += acc[mt][nt][0] * adv[nt].x + acc[mt][nt][1] * adv[nt].y;
                su_hi += acc[mt][nt][2] * asv[nt].x + acc[mt][nt][3] * asv[nt].y;
                du_hi += acc[mt][nt][2] * adv[nt].x + acc[mt][nt][3] * adv[nt].y;
            }
        }
        if (is1) {
#pragma unroll
            for (int off = 1; off <= 2; off <<= 1) {
                su_lo += __shfl_xor_sync(0xffffffffu, su_lo, off);
                du_lo += __shfl_xor_sync(0xffffffffu, du_lo, off);
                su_hi += __shfl_xor_sync(0xffffffffu, su_hi, off);
                du_hi += __shfl_xor_sync(0xffffffffu, du_hi, off);
            }
            if (t == 0) {
                if (r_lo < NN) { ssrc[r_lo * HEADS + wn] = su_lo; sdst[r_lo * HEADS + wn] = du_lo; }
                if (r_hi < NN) { ssrc[r_hi * HEADS + wn] = su_hi; sdst[r_hi * HEADS + wn] = du_hi; }
            }
        }
    }
}

// ---------------- softmax + aggregation ------------------------------------------
__device__ __forceinline__ float lrelu(float v) { return v > 0.f ? v : NEG_SLOPE * v; }

template<int LAYER>
__global__ void __launch_bounds__(256) agg_kernel(
    const float* __restrict__ h,
    const float* __restrict__ ss,
    const float* __restrict__ sd,
    const float* __restrict__ bias,
    float* __restrict__ out,
    const float* __restrict__ xr,
    const float* __restrict__ br)
{
    __shared__ float epl[8][4][CAP + 1];  // per-head planar exp logits
    __shared__ int   srcc[8][CAP];

    int warp = (blockIdx.x * blockDim.x + threadIdx.x) >> 5;
    int wip  = threadIdx.x >> 5;
    int lane = threadIdx.x & 31;
    if (warp >= NN) return;
    int n = warp;
    int begin = g_offs[n], end = g_offs[n + 1];
    int deg = end - begin;
    if (LAYER == 2 && lane == 0) g_deg[n] = 0;   // reset for next launch/replay

    float4 sdv = *(const float4*)&sd[n * HEADS];
    float4 ssn = *(const float4*)&ss[n * HEADS];
    float4 els = make_float4(lrelu(ssn.x + sdv.x), lrelu(ssn.y + sdv.y),
                             lrelu(ssn.z + sdv.z), lrelu(ssn.w + sdv.w));
    float m0 = els.x, m1 = els.y, m2 = els.z, m3 = els.w;
    float d0 = 0.f, d1 = 0.f, d2 = 0.f, d3 = 0.f;

    int hd = lane >> 3;
    int c0 = lane * 4;

    if (deg <= CAP) {
        // pass 1: gather scores, planar logits, track max
        for (int i = lane; i < deg; i += 32) {
            int s = g_sorted_src[begin + i];
            float4 sv = *(const float4*)&ss[s * HEADS];
            float e0 = lrelu(sv.x + sdv.x), e1 = lrelu(sv.y + sdv.y);
            float e2 = lrelu(sv.z + sdv.z), e3 = lrelu(sv.w + sdv.w);
            epl[wip][0][i] = e0; epl[wip][1][i] = e1;
            epl[wip][2][i] = e2; epl[wip][3][i] = e3;
            srcc[wip][i] = s;
            m0 = fmaxf(m0, e0); m1 = fmaxf(m1, e1);
            m2 = fmaxf(m2, e2); m3 = fmaxf(m3, e3);
        }
#pragma unroll
        for (int off = 16; off; off >>= 1) {
            m0 = fmaxf(m0, __shfl_xor_sync(0xffffffffu, m0, off));
            m1 = fmaxf(m1, __shfl_xor_sync(0xffffffffu, m1, off));
            m2 = fmaxf(m2, __shfl_xor_sync(0xffffffffu, m2, off));
            m3 = fmaxf(m3, __shfl_xor_sync(0xffffffffu, m3, off));
        }
        __syncwarp();
        // pass 2: exponentiate in smem, accumulate denominator
        for (int i = lane; i < deg; i += 32) {
            float e0 = __expf(epl[wip][0][i] - m0);
            float e1 = __expf(epl[wip][1][i] - m1);
            float e2 = __expf(epl[wip][2][i] - m2);
            float e3 = __expf(epl[wip][3][i] - m3);
            epl[wip][0][i] = e0; epl[wip][1][i] = e1;
            epl[wip][2][i] = e2; epl[wip][3][i] = e3;
            d0 += e0; d1 += e1; d2 += e2; d3 += e3;
        }
#pragma unroll
        for (int off = 16; off; off >>= 1) {
            d0 += __shfl_xor_sync(0xffffffffu, d0, off);
            d1 += __shfl_xor_sync(0xffffffffu, d1, off);
            d2 += __shfl_xor_sync(0xffffffffu, d2, off);
            d3 += __shfl_xor_sync(0xffffffffu, d3, off);
        }
        float es0 = __expf(els.x - m0), es1 = __expf(els.y - m1);
        float es2 = __expf(els.z - m2), es3 = __expf(els.w - m3);
        d0 += es0; d1 += es1; d2 += es2; d3 += es3;
        __syncwarp();

        // pass 3: unnormalized weighted gather; normalize at the end
        float dh  = (hd == 0) ? d0 : (hd == 1) ? d1 : (hd == 2) ? d2 : d3;
        float esh = (hd == 0) ? es0 : (hd == 1) ? es1 : (hd == 2) ? es2 : es3;
        float inv_dh = 1.f / dh;

        float4 hn = *(const float4*)&h[(long long)n * D + c0];
        float ax = esh * hn.x, ay = esh * hn.y, az = esh * hn.z, aw = esh * hn.w;

        const float* __restrict__ ep = &epl[wip][hd][0];
        const int*   __restrict__ sp = &srcc[wip][0];
#pragma unroll 4
        for (int i = 0; i < deg; ++i) {
            float e = ep[i];
            int s = sp[i];
            float4 hv = *(const float4*)&h[(long long)s * D + c0];
            ax += e * hv.x; ay += e * hv.y; az += e * hv.z; aw += e * hv.w;
        }
        ax *= inv_dh; ay *= inv_dh; az *= inv_dh; aw *= inv_dh;

        float4 b = *(const float4*)&bias[c0];
        if (LAYER == 1) {
            float4 o = make_float4(fmaxf(ax + b.x, 0.f), fmaxf(ay + b.y, 0.f),
                                   fmaxf(az + b.z, 0.f), fmaxf(aw + b.w, 0.f));
            *(float4*)&out[(long long)n * D + c0] = o;
        } else {
            float4 r  = *(const float4*)&xr[(long long)n * D + c0];
            float4 bb = *(const float4*)&br[c0];
            float4 o = make_float4(ax + b.x + r.x + bb.x, ay + b.y + r.y + bb.y,
                                   az + b.z + r.z + bb.z, aw + b.w + r.w + bb.w);
            *(float4*)&out[(long long)n * D + c0] = o;
        }
        return;
    }

    // ---- fallback (deg > CAP; statistically unreachable): global recompute ----
    for (int e = begin + lane; e < end; e += 32) {
        int s = g_sorted_src[e];
        float4 sv = *(const float4*)&ss[s * HEADS];
        m0 = fmaxf(m0, lrelu(sv.x + sdv.x)); m1 = fmaxf(m1, lrelu(sv.y + sdv.y));
        m2 = fmaxf(m2, lrelu(sv.z + sdv.z)); m3 = fmaxf(m3, lrelu(sv.w + sdv.w));
    }
#pragma unroll
    for (int off = 16; off; off >>= 1) {
        m0 = fmaxf(m0, __shfl_xor_sync(0xffffffffu, m0, off));
        m1 = fmaxf(m1, __shfl_xor_sync(0xffffffffu, m1, off));
        m2 = fmaxf(m2, __shfl_xor_sync(0xffffffffu, m2, off));
        m3 = fmaxf(m3, __shfl_xor_sync(0xffffffffu, m3, off));
    }
    for (int e = begin + lane; e < end; e += 32) {
        int s = g_sorted_src[e];
        float4 sv = *(const float4*)&ss[s * HEADS];
        d0 += __expf(lrelu(sv.x + sdv.x) - m0);
        d1 += __expf(lrelu(sv.y + sdv.y) - m1);
        d2 += __expf(lrelu(sv.z + sdv.z) - m2);
        d3 += __expf(lrelu(sv.w + sdv.w) - m3);
    }
#pragma unroll
    for (int off = 16; off; off >>= 1) {
        d0 += __shfl_xor_sync(0xffffffffu, d0, off);
        d1 += __shfl_xor_sync(0xffffffffu, d1, off);
        d2 += __shfl_xor_sync(0xffffffffu, d2, off);
        d3 += __shfl_xor_sync(0xffffffffu, d3, off);
    }
    float es0 = __expf(els.x - m0), es1 = __expf(els.y - m1);
    float es2 = __expf(els.z - m2), es3 = __expf(els.w - m3);
    d0 += es0; d1 += es1; d2 += es2; d3 += es3;

    float mh  = (hd == 0) ? m0 : (hd == 1) ? m1 : (hd == 2) ? m2 : m3;
    float dh  = (hd == 0) ? d0 : (hd == 1) ? d1 : (hd == 2) ? d2 : d3;
    float esh = (hd == 0) ? es0 : (hd == 1) ? es1 : (hd == 2) ? es2 : es3;
    float sdh = (hd == 0) ? sdv.x : (hd == 1) ? sdv.y : (hd == 2) ? sdv.z : sdv.w;
    float inv_dh = 1.f / dh;

    float4 hn = *(const float4*)&h[(long long)n * D + c0];
    float ax = esh * hn.x, ay = esh * hn.y, az = esh * hn.z, aw = esh * hn.w;
    for (int e = begin; e < end; ++e) {
        int s = g_sorted_src[e];
        float el = lrelu(ss[s * HEADS + hd] + sdh);
        float w = __expf(el - mh);
        float4 hv = *(const float4*)&h[(long long)s * D + c0];
        ax += w * hv.x; ay += w * hv.y; az += w * hv.z; aw += w * hv.w;
    }
    ax *= inv_dh; ay *= inv_dh; az *= inv_dh; aw *= inv_dh;

    float4 b = *(const float4*)&bias[c0];
    if (LAYER == 1) {
        float4 o = make_float4(fmaxf(ax + b.x, 0.f), fmaxf(ay + b.y, 0.f),
                               fmaxf(az + b.z, 0.f), fmaxf(aw + b.w, 0.f));
        *(float4*)&out[(long long)n * D + c0] = o;
    } else {
        float4 r  = *(const float4*)&xr[(long long)n * D + c0];
        float4 bb = *(const float4*)&br[c0];
        float4 o = make_float4(ax + b.x + r.x + bb.x, ay + b.y + r.y + bb.y,
                               az + b.z + r.z + bb.z, aw + b.w + r.w + bb.w);
        *(float4*)&out[(long long)n * D + c0] = o;
    }
}

// ---------------- launch ----------------------------------------------------------
extern "C" void kernel_launch(void* const* d_in, const int* in_sizes, int n_in,
                              void* d_out, int out_size) {
    const float* x   = (const float*)d_in[0];
    const void*  ei  = d_in[1];
    const float* W1  = (const float*)d_in[2];
    const float* a1s = (const float*)d_in[3];
    const float* a1d = (const float*)d_in[4];
    const float* b1  = (const float*)d_in[5];
    const float* W2  = (const float*)d_in[6];
    const float* a2s = (const float*)d_in[7];
    const float* a2d = (const float*)d_in[8];
    const float* b2  = (const float*)d_in[9];
    const float* Wr  = (const float*)d_in[10];
    const float* br  = (const float*)d_in[11];
    float* out = (float*)d_out;

    float* bufA; cudaGetSymbolAddress((void**)&bufA, g_bufA);
    float* bufB; cudaGetSymbolAddress((void**)&bufB, g_bufB);
    float* xr;   cudaGetSymbolAddress((void**)&xr, g_xr);
    float* ssp;  cudaGetSymbolAddress((void**)&ssp, g_ss);
    float* sdp;  cudaGetSymbolAddress((void**)&sdp, g_sd);

    // edge preprocessing: compact counting sort (g_deg zeroed by agg2 / static init)
    count_kernel<<<(EE + 255) / 256, 256>>>(ei);
    scan_k1<<<NB_SCAN, 256>>>();
    scan_k2<<<1, 128>>>();
    scan_k3<<<NB_SCAN, 256>>>();
    scatter_kernel<<<(EE + 255) / 256, 256>>>(ei);

    // layer-1 transform + residual transform fused (reads x once)
    gemm_dual_kernel<<<(NN + 127) / 128, 512>>>(x, W1, Wr, a1s, a1d,
                                                bufA, xr, ssp, sdp);
    // layer-1 aggregation
    agg_kernel<1><<<(NN + 7) / 8, 256>>>(bufA, ssp, sdp, b1, bufB, nullptr, nullptr);
    // layer-2 transform + scores
    gemm_tc_kernel<true><<<(NN + 127) / 128, 256>>>(bufB, W2, a2s, a2d, bufA, ssp, sdp);
    // layer-2 aggregation + residual (+ deg reset)
    agg_kernel<2><<<(NN + 7) / 8, 256>>>(bufA, ssp, sdp, b2, out, xr, br);
}